// round 4
// baseline (speedup 1.0000x reference)
#include <cuda_runtime.h>
#include <cuda_bf16.h>
#include <cstdint>

#define BATCH  64
#define TSTEPS 2048
#define M_ROWS (BATCH * TSTEPS)   // 131072
#define HID    64
#define G4     256

typedef unsigned long long ull;

// ---------------------------------------------------------------------------
// Scratch
// ---------------------------------------------------------------------------
__device__ float    g_xg1[(size_t)M_ROWS * G4];   // layer1 gate preacts, PAIR layout
__device__ float    g_xg2[(size_t)M_ROWS * G4];   // layer2 gate preacts, PAIR layout
__device__ uint32_t g_xph[(size_t)M_ROWS * 64];   // x packed bf16x2 (hi)
__device__ uint32_t g_xpl[(size_t)M_ROWS * 64];   // x packed bf16x2 (lo residual)
__device__ uint4    g_wf1[32 * 8 * 32];           // W_ih1 fragment-ordered (hi+lo)
__device__ unsigned g_flag[BATCH];                // producer progress (rows ready)

// Pair layout for xg: 128 ull per row; slot s<64 = {i_s,f_s}; slot 64+s = {g_s,o_s}.

// ---------------------------------------------------------------------------
// Helpers
// ---------------------------------------------------------------------------
__device__ __forceinline__ uint32_t packbf(float lo, float hi) {
    uint32_t r;
    asm("cvt.rn.bf16x2.f32 %0, %1, %2;" : "=r"(r) : "f"(hi), "f"(lo));
    return r;
}
__device__ __forceinline__ ull pack64(float lo, float hi) {
    ull r; asm("mov.b64 %0, {%1, %2};" : "=l"(r) : "f"(lo), "f"(hi)); return r;
}
__device__ __forceinline__ void unpack64(ull v, float& lo, float& hi) {
    asm("mov.b64 {%0, %1}, %2;" : "=f"(lo), "=f"(hi) : "l"(v));
}
__device__ __forceinline__ void fma2(ull& acc, ull a, ull b) {
    asm("fma.rn.f32x2 %0, %1, %2, %0;" : "+l"(acc) : "l"(a), "l"(b));
}
__device__ __forceinline__ ull add2(ull a, ull b) {
    ull r; asm("add.rn.f32x2 %0, %1, %2;" : "=l"(r) : "l"(a), "l"(b)); return r;
}
__device__ __forceinline__ float bf16_round(float f) {
    return __bfloat162float(__float2bfloat16_rn(f));
}

// ---- MUFU-free activations -----------------------------------------------
// e^z for z <= 0 (clamped at -87): magic-rint + deg-6 Taylor + exponent bit-add.
__device__ __forceinline__ float exp_negf(float z) {
    const float L2E = 1.4426950408889634f;
    const float MAGIC = 12582912.0f;           // 1.5 * 2^23
    float t  = fmaxf(z, -87.0f);
    float k  = fmaf(t, L2E, MAGIC);
    int   ik = __float_as_int(k) - 0x4B400000; // = rint(t * L2E)
    float fi = k - MAGIC;
    float f  = fmaf(t, L2E, -fi);              // in [-0.5, 0.5]
    float w  = f * 0.6931471805599453f;
    float p  = 1.3888889e-3f;
    p = fmaf(p, w, 8.3333333e-3f);
    p = fmaf(p, w, 4.1666667e-2f);
    p = fmaf(p, w, 1.6666667e-1f);
    p = fmaf(p, w, 0.5f);
    p = fmaf(p, w, 1.0f);
    p = fmaf(p, w, 1.0f);
    return __int_as_float(__float_as_int(p) + (ik << 23));
}
// 1/d for d in (1, 2]: bit-trick init + 3 Newton (err < 1e-9)
__device__ __forceinline__ float rcp12(float d) {
    float r = __int_as_float(0x7EF311C3 - __float_as_int(d));
    r = r * fmaf(-d, r, 2.0f);
    r = r * fmaf(-d, r, 2.0f);
    r = r * fmaf(-d, r, 2.0f);
    return r;
}
__device__ __forceinline__ float sigf(float x) {
    float e = exp_negf(-fabsf(x));
    float r = rcp12(1.0f + e);
    return (x >= 0.0f) ? r : e * r;
}
__device__ __forceinline__ float tanhf_fast(float x) {
    float e = exp_negf(-2.0f * fabsf(x));
    float r = rcp12(1.0f + e);
    float th = fmaf(-e, r, r);                 // (1-e)/(1+e) = tanh(|x|)
    return __int_as_float(__float_as_int(th) |
                          (__float_as_int(x) & 0x80000000));
}

__device__ __forceinline__ void mma16816(float* c, const uint32_t* a,
                                         uint32_t b0, uint32_t b1) {
    asm("mma.sync.aligned.m16n8k16.row.col.f32.bf16.bf16.f32 "
        "{%0,%1,%2,%3}, {%4,%5,%6,%7}, {%8,%9}, {%0,%1,%2,%3};"
        : "+f"(c[0]), "+f"(c[1]), "+f"(c[2]), "+f"(c[3])
        : "r"(a[0]), "r"(a[1]), "r"(a[2]), "r"(a[3]), "r"(b0), "r"(b1));
}
__device__ __forceinline__ unsigned ld_acq(const unsigned* p) {
    unsigned v;
    asm volatile("ld.acquire.gpu.global.u32 %0, [%1];" : "=r"(v) : "l"(p) : "memory");
    return v;
}
__device__ __forceinline__ void st_rel(unsigned* p, unsigned v) {
    asm volatile("st.release.gpu.global.u32 [%0], %1;" :: "l"(p), "r"(v) : "memory");
}

// 64-long packed dot: vectorized LDS.128 (2 packed pairs per load)
__device__ __forceinline__ ull dot64v(const ull* hp_, const ull* wv) {
    const ulonglong2* hp = (const ulonglong2*)hp_;
    ull a0 = 0ull, a1 = 0ull, a2 = 0ull, a3 = 0ull;
#pragma unroll
    for (int k = 0; k < 32; k += 2) {
        ulonglong2 v0 = hp[k];
        ulonglong2 v1 = hp[k + 1];
        fma2(a0, v0.x, wv[2 * k]);
        fma2(a1, v0.y, wv[2 * k + 1]);
        fma2(a2, v1.x, wv[2 * k + 2]);
        fma2(a3, v1.y, wv[2 * k + 3]);
    }
    return add2(add2(a0, a1), add2(a2, a3));
}

// ---------------------------------------------------------------------------
// Prep kernels
// ---------------------------------------------------------------------------
__global__ void prep_x_kernel(const float* __restrict__ x) {
    int i = blockIdx.x * blockDim.x + threadIdx.x;
    if (i < BATCH) g_flag[i] = 0;
    if (i >= M_ROWS * 64) return;
    float2 f = ((const float2*)x)[i];
    float hx = bf16_round(f.x), hy = bf16_round(f.y);
    g_xph[i] = packbf(f.x, f.y);
    g_xpl[i] = packbf(f.x - hx, f.y - hy);
}

__global__ void prep_w_kernel(const float* __restrict__ W) {
    const int KI = 8, K = 128;
    int total = 32 * KI * 32;
    int i = blockIdx.x * blockDim.x + threadIdx.x;
    if (i >= total) return;
    int lane = i & 31;
    int ki   = (i >> 5) % KI;
    int nt   = i / (32 * KI);
    int tig = lane & 3, gid = lane >> 2;
    int n  = nt * 8 + gid;
    int k0 = ki * 16 + tig * 2;
    const float* Wn = W + (size_t)n * K;
    float w00 = Wn[k0],     w01 = Wn[k0 + 1];
    float w10 = Wn[k0 + 8], w11 = Wn[k0 + 9];
    uint4 v;
    v.x = packbf(w00, w01);
    v.y = packbf(w10, w11);
    v.z = packbf(w00 - bf16_round(w00), w01 - bf16_round(w01));
    v.w = packbf(w10 - bf16_round(w10), w11 - bf16_round(w11));
    g_wf1[(nt * KI + ki) * 32 + lane] = v;
}

// ---------------------------------------------------------------------------
// GEMM1: g_xg1 = x @ W_ih1^T + bias (3-term bf16 split, pair-layout epilogue)
// ---------------------------------------------------------------------------
__device__ __forceinline__ void st_pair(float* base, size_t r, int c, float v) {
    int slot = (c & 63) + ((c & 128) ? 64 : 0);
    int e    = (c >> 6) & 1;
    base[r * G4 + slot * 2 + e] = v;
}

__global__ __launch_bounds__(256, 2) void gemm_kernel(
    const float* __restrict__ bias_a, const float* __restrict__ bias_b)
{
    const int KI = 8, PPR = 64;
    int tid = threadIdx.x;
    int lane = tid & 31, wid = tid >> 5;
    int tig = lane & 3, gid = lane >> 2;
    int wm = wid & 3, wn = wid >> 2;
    int rb = blockIdx.x * 64 + wm * 16;
    int ntBase = (blockIdx.y * 2 + wn) * 8;

    float acc[8][4];
#pragma unroll
    for (int j = 0; j < 8; j++)
#pragma unroll
        for (int q = 0; q < 4; q++) acc[j][q] = 0.0f;

#pragma unroll
    for (int ki = 0; ki < KI; ki++) {
        uint32_t a[4], al[4];
        size_t r0 = (size_t)(rb + gid) * PPR + ki * 8;
        a[0]  = __ldg(g_xph + r0 + tig);
        a[1]  = __ldg(g_xph + r0 + 8 * PPR + tig);
        a[2]  = __ldg(g_xph + r0 + 4 + tig);
        a[3]  = __ldg(g_xph + r0 + 8 * PPR + 4 + tig);
        al[0] = __ldg(g_xpl + r0 + tig);
        al[1] = __ldg(g_xpl + r0 + 8 * PPR + tig);
        al[2] = __ldg(g_xpl + r0 + 4 + tig);
        al[3] = __ldg(g_xpl + r0 + 8 * PPR + 4 + tig);
#pragma unroll
        for (int j = 0; j < 8; j++) {
            uint4 bf = __ldg(&g_wf1[((ntBase + j) * KI + ki) * 32 + lane]);
            mma16816(acc[j], a,  bf.x, bf.y);
            mma16816(acc[j], a,  bf.z, bf.w);
            mma16816(acc[j], al, bf.x, bf.y);
        }
    }

#pragma unroll
    for (int j = 0; j < 8; j++) {
        int nc = (ntBase + j) * 8 + tig * 2;
        float bs0 = __ldg(bias_a + nc) + __ldg(bias_b + nc);
        float bs1 = __ldg(bias_a + nc + 1) + __ldg(bias_b + nc + 1);
        size_t r = (size_t)(rb + gid);
        st_pair(g_xg1, r,     nc,     acc[j][0] + bs0);
        st_pair(g_xg1, r,     nc + 1, acc[j][1] + bs1);
        st_pair(g_xg1, r + 8, nc,     acc[j][2] + bs0);
        st_pair(g_xg1, r + 8, nc + 1, acc[j][3] + bs1);
    }
}

// ---------------------------------------------------------------------------
// Fused pipelined recurrence (see R2 comment). Changes:
//  - MUFU-free activations
//  - LDS.128 dot products
//  - mask1 folded into GEMV weights (hqm buffer removed)
// ---------------------------------------------------------------------------
__global__ __launch_bounds__(256, 1) void fused_rec_kernel(
    const float* __restrict__ Whh1, const float* __restrict__ mask1,
    const float* __restrict__ Wih2, const float* __restrict__ bih2,
    const float* __restrict__ bhh2,
    const float* __restrict__ Whh2, const float* __restrict__ mask2,
    float* __restrict__ out)
{
    __shared__ alignas(16) ull hq[2][64];   // duplicated h: {h,h}

    int tid  = threadIdx.x;
    int bid  = blockIdx.x;
    bool producer = bid < BATCH;
    int b = producer ? bid : bid - BATCH;

    if (producer) {
        if (tid < 128) {
            // ---- layer1 recurrence warps ----
            int lane = tid & 31, w = tid >> 5;
            int jj = (w << 4) + (lane & 15);
            bool isIF = lane < 16;
            int rA = isIF ? jj : 128 + jj;
            ull wv[64];
#pragma unroll
            for (int k = 0; k < 64; k++)
                wv[k] = pack64(__ldg(Whh1 + (size_t)rA * 64 + k),
                               __ldg(Whh1 + (size_t)(rA + 64) * 64 + k));
            if (tid < 64) { hq[0][tid] = 0ull; hq[1][tid] = 0ull; }
            float c = 0.0f;
            const ull* xgb = (const ull*)g_xg1 + (size_t)b * TSTEPS * 128
                             + (isIF ? jj : 64 + jj);
            __syncthreads();                               // bar0
            ull xc = __ldg(xgb), xn = __ldg(xgb + 128);
            for (int t = 0; t < TSTEPS; t++) {
                int p = t & 1;
                ull xf = 0ull;
                if (t + 2 < TSTEPS) xf = __ldg(xgb + (size_t)(t + 2) * 128);
                ull s = add2(dot64v(hq[p], wv), xc);
                float gA, gB; unpack64(s, gA, gB);
                float A0, A1;
                if (isIF) { A0 = sigf(gA);       A1 = sigf(gB); }
                else      { A0 = tanhf_fast(gA); A1 = sigf(gB); }
                float sg = __shfl_xor_sync(0xffffffffu, A0, 16);
                float so = __shfl_xor_sync(0xffffffffu, A1, 16);
                if (isIF) {
                    c = A1 * c + A0 * sg;
                    float h = so * tanhf_fast(c);
                    hq[p ^ 1][jj] = pack64(h, h);
                }
                xc = xn; xn = xf;
                __syncthreads();                           // 1 bar / step
            }
            __syncthreads();                               // post (match gemv)
        } else {
            // ---- GEMV warps: xg2 row t-1 = (W_ih2 * mask1) @ h(t-1) + bias ----
            int s = tid - 128;                             // pair slot 0..127
            int rA = (s < 64) ? s : 128 + (s - 64);
            ull wxv[64];
#pragma unroll
            for (int k = 0; k < 64; k++) {
                float m = __ldg(mask1 + b * 64 + k);
                wxv[k] = pack64(__ldg(Wih2 + (size_t)rA * 64 + k) * m,
                                __ldg(Wih2 + (size_t)(rA + 64) * 64 + k) * m);
            }
            ull bias = pack64(__ldg(bih2 + rA) + __ldg(bhh2 + rA),
                              __ldg(bih2 + rA + 64) + __ldg(bhh2 + rA + 64));
            ull* dst = (ull*)g_xg2 + (size_t)b * TSTEPS * 128 + s;
            __syncthreads();                               // bar0
            for (int t = 0; t < TSTEPS; t++) {
                int p = t & 1;
                if (t > 0) {
                    ull sum = add2(dot64v(hq[p], wxv), bias);
                    dst[(size_t)(t - 1) * 128] = sum;
                }
                if (tid == 128 && t > 0 && (t & 15) == 0) {
                    __threadfence();
                    st_rel(&g_flag[b], (unsigned)(t - 1)); // rows 0..t-2 ready
                }
                __syncthreads();
            }
            {   // final row T-1
                ull sum = add2(dot64v(hq[TSTEPS & 1], wxv), bias);
                dst[(size_t)(TSTEPS - 1) * 128] = sum;
            }
            __syncthreads();                               // post
            if (tid == 128) {
                __threadfence();
                st_rel(&g_flag[b], (unsigned)TSTEPS);
            }
        }
    } else {
        // =================== CONSUMER: layer2 ===================
        if (tid < 128) {
            int lane = tid & 31, w = tid >> 5;
            int jj = (w << 4) + (lane & 15);
            bool isIF = lane < 16;
            int rA = isIF ? jj : 128 + jj;
            ull wv[64];
#pragma unroll
            for (int k = 0; k < 64; k++)
                wv[k] = pack64(__ldg(Whh2 + (size_t)rA * 64 + k),
                               __ldg(Whh2 + (size_t)(rA + 64) * 64 + k));
            float mval = __ldg(mask2 + b * 64 + jj);
            if (tid < 64) { hq[0][tid] = 0ull; hq[1][tid] = 0ull; }
            float c = 0.0f;
            const ull* xgb = (const ull*)g_xg2 + (size_t)b * TSTEPS * 128
                             + (isIF ? jj : 64 + jj);
            unsigned avail = 0;
            __syncthreads();                               // bar0
            while (avail < 2u) { avail = ld_acq(&g_flag[b]); if (avail < 2u) __nanosleep(64); }
            ull xc = xgb[0], xn = xgb[128];
            for (int t = 0; t < TSTEPS; t++) {
                int p = t & 1;
                ull xf = 0ull;
                if (t + 2 < TSTEPS) {
                    unsigned need = (unsigned)(t + 3);
                    while (avail < need) { avail = ld_acq(&g_flag[b]); if (avail < need) __nanosleep(64); }
                    xf = xgb[(size_t)(t + 2) * 128];
                }
                ull s = add2(dot64v(hq[p], wv), xc);
                float gA, gB; unpack64(s, gA, gB);
                float A0, A1;
                if (isIF) { A0 = sigf(gA);       A1 = sigf(gB); }
                else      { A0 = tanhf_fast(gA); A1 = sigf(gB); }
                float sg = __shfl_xor_sync(0xffffffffu, A0, 16);
                float so = __shfl_xor_sync(0xffffffffu, A1, 16);
                if (isIF) {
                    c = A1 * c + A0 * sg;
                    float h = so * tanhf_fast(c);
                    hq[p ^ 1][jj] = pack64(h, h);
                    out[((size_t)b * TSTEPS + t) * HID + jj] = fmaxf(h * mval, 0.0f);
                }
                xc = xn; xn = xf;
                __syncthreads();
            }
        } else {
            __syncthreads();                               // bar0
            for (int t = 0; t < TSTEPS; t++) __syncthreads();
        }
    }
}

// ---------------------------------------------------------------------------
// Launch
// ---------------------------------------------------------------------------
extern "C" void kernel_launch(void* const* d_in, const int* in_sizes, int n_in,
                              void* d_out, int out_size) {
    const float* x     = (const float*)d_in[0];
    const float* W_ih1 = (const float*)d_in[1];
    const float* W_hh1 = (const float*)d_in[2];
    const float* b_ih1 = (const float*)d_in[3];
    const float* b_hh1 = (const float*)d_in[4];
    const float* W_ih2 = (const float*)d_in[5];
    const float* W_hh2 = (const float*)d_in[6];
    const float* b_ih2 = (const float*)d_in[7];
    const float* b_hh2 = (const float*)d_in[8];
    const float* mask1 = (const float*)d_in[9];
    const float* mask2 = (const float*)d_in[10];
    float* out = (float*)d_out;

    prep_x_kernel<<<(M_ROWS * 64) / 256, 256>>>(x);
    prep_w_kernel<<<(32 * 8 * 32 + 127) / 128, 128>>>(W_ih1);
    gemm_kernel<<<dim3(M_ROWS / 64, 2), 256>>>(b_ih1, b_hh1);
    fused_rec_kernel<<<2 * BATCH, 256>>>(W_hh1, mask1, W_ih2, b_ih2, b_hh2,
                                         W_hh2, mask2, out);
}

// round 5
// speedup vs baseline: 1.8177x; 1.8177x over previous
#include <cuda_runtime.h>
#include <cuda_bf16.h>
#include <cstdint>

#define BATCH  64
#define TSTEPS 2048
#define M_ROWS (BATCH * TSTEPS)   // 131072
#define HID    64
#define G4     256

typedef unsigned long long ull;

// ---------------------------------------------------------------------------
// Scratch
// ---------------------------------------------------------------------------
__device__ float    g_xg1[(size_t)M_ROWS * G4];   // layer1 gate preacts, PAIR layout
__device__ float    g_xg2[(size_t)M_ROWS * G4];   // layer2 gate preacts, PAIR layout
__device__ uint32_t g_xph[(size_t)M_ROWS * 64];   // x packed bf16x2 (hi)
__device__ uint32_t g_xpl[(size_t)M_ROWS * 64];   // x packed bf16x2 (lo residual)
__device__ uint4    g_wf1[32 * 8 * 32];           // W_ih1 fragment-ordered (hi+lo)
__device__ unsigned g_flag[BATCH];                // producer progress (rows ready)

// Pair layout for xg: 128 ull per row; slot s<64 = {i_s,f_s}; slot 64+s = {g_s,o_s}.

// ---------------------------------------------------------------------------
// Helpers
// ---------------------------------------------------------------------------
__device__ __forceinline__ uint32_t packbf(float lo, float hi) {
    uint32_t r;
    asm("cvt.rn.bf16x2.f32 %0, %1, %2;" : "=r"(r) : "f"(hi), "f"(lo));
    return r;
}
__device__ __forceinline__ ull pack64(float lo, float hi) {
    ull r; asm("mov.b64 %0, {%1, %2};" : "=l"(r) : "f"(lo), "f"(hi)); return r;
}
__device__ __forceinline__ void unpack64(ull v, float& lo, float& hi) {
    asm("mov.b64 {%0, %1}, %2;" : "=f"(lo), "=f"(hi) : "l"(v));
}
__device__ __forceinline__ void fma2(ull& acc, ull a, ull b) {
    asm("fma.rn.f32x2 %0, %1, %2, %0;" : "+l"(acc) : "l"(a), "l"(b));
}
__device__ __forceinline__ ull add2(ull a, ull b) {
    ull r; asm("add.rn.f32x2 %0, %1, %2;" : "=l"(r) : "l"(a), "l"(b)); return r;
}
__device__ __forceinline__ float bf16_round(float f) {
    return __bfloat162float(__float2bfloat16_rn(f));
}

// ---- Activations: single-MUFU tanh.approx ---------------------------------
__device__ __forceinline__ float tanh_mufu(float x) {
    float y; asm("tanh.approx.f32 %0, %1;" : "=f"(y) : "f"(x)); return y;
}
__device__ __forceinline__ float sig_mufu(float x) {
    return fmaf(tanh_mufu(x * 0.5f), 0.5f, 0.5f);
}

__device__ __forceinline__ void mma16816(float* c, const uint32_t* a,
                                         uint32_t b0, uint32_t b1) {
    asm("mma.sync.aligned.m16n8k16.row.col.f32.bf16.bf16.f32 "
        "{%0,%1,%2,%3}, {%4,%5,%6,%7}, {%8,%9}, {%0,%1,%2,%3};"
        : "+f"(c[0]), "+f"(c[1]), "+f"(c[2]), "+f"(c[3])
        : "r"(a[0]), "r"(a[1]), "r"(a[2]), "r"(a[3]), "r"(b0), "r"(b1));
}
__device__ __forceinline__ unsigned ld_acq(const unsigned* p) {
    unsigned v;
    asm volatile("ld.acquire.gpu.global.u32 %0, [%1];" : "=r"(v) : "l"(p) : "memory");
    return v;
}
__device__ __forceinline__ void st_rel(unsigned* p, unsigned v) {
    asm volatile("st.release.gpu.global.u32 [%0], %1;" :: "l"(p), "r"(v) : "memory");
}

// 64-pair packed dot, software-pipelined: double-buffered chunks of 4 LDS.128
// so shared-memory latency hides behind the previous chunk's FFMA2s.
__device__ __forceinline__ ull dot64p(const ull* hp_, const ull* wv) {
    const ulonglong2* hp = (const ulonglong2*)hp_;
    ulonglong2 bufA[4], bufB[4];
#pragma unroll
    for (int i = 0; i < 4; i++) bufA[i] = hp[i];
    ull a0 = 0ull, a1 = 0ull, a2 = 0ull, a3 = 0ull;
#pragma unroll
    for (int c = 0; c < 8; c++) {
        ulonglong2* cur = (c & 1) ? bufB : bufA;
        ulonglong2* nxt = (c & 1) ? bufA : bufB;
        if (c < 7) {
#pragma unroll
            for (int i = 0; i < 4; i++) nxt[i] = hp[(c + 1) * 4 + i];
        }
        fma2(a0, cur[0].x, wv[c * 8 + 0]);
        fma2(a1, cur[0].y, wv[c * 8 + 1]);
        fma2(a2, cur[1].x, wv[c * 8 + 2]);
        fma2(a3, cur[1].y, wv[c * 8 + 3]);
        fma2(a0, cur[2].x, wv[c * 8 + 4]);
        fma2(a1, cur[2].y, wv[c * 8 + 5]);
        fma2(a2, cur[3].x, wv[c * 8 + 6]);
        fma2(a3, cur[3].y, wv[c * 8 + 7]);
    }
    return add2(add2(a0, a1), add2(a2, a3));
}

// ---------------------------------------------------------------------------
// Prep kernels
// ---------------------------------------------------------------------------
__global__ void prep_x_kernel(const float* __restrict__ x) {
    int i = blockIdx.x * blockDim.x + threadIdx.x;
    if (i < BATCH) g_flag[i] = 0;
    if (i >= M_ROWS * 64) return;
    float2 f = ((const float2*)x)[i];
    float hx = bf16_round(f.x), hy = bf16_round(f.y);
    g_xph[i] = packbf(f.x, f.y);
    g_xpl[i] = packbf(f.x - hx, f.y - hy);
}

__global__ void prep_w_kernel(const float* __restrict__ W) {
    const int KI = 8, K = 128;
    int total = 32 * KI * 32;
    int i = blockIdx.x * blockDim.x + threadIdx.x;
    if (i >= total) return;
    int lane = i & 31;
    int ki   = (i >> 5) % KI;
    int nt   = i / (32 * KI);
    int tig = lane & 3, gid = lane >> 2;
    int n  = nt * 8 + gid;
    int k0 = ki * 16 + tig * 2;
    const float* Wn = W + (size_t)n * K;
    float w00 = Wn[k0],     w01 = Wn[k0 + 1];
    float w10 = Wn[k0 + 8], w11 = Wn[k0 + 9];
    uint4 v;
    v.x = packbf(w00, w01);
    v.y = packbf(w10, w11);
    v.z = packbf(w00 - bf16_round(w00), w01 - bf16_round(w01));
    v.w = packbf(w10 - bf16_round(w10), w11 - bf16_round(w11));
    g_wf1[(nt * KI + ki) * 32 + lane] = v;
}

// ---------------------------------------------------------------------------
// GEMM1: g_xg1 = x @ W_ih1^T + bias (3-term bf16 split, pair-layout epilogue)
// ---------------------------------------------------------------------------
__device__ __forceinline__ void st_pair(float* base, size_t r, int c, float v) {
    int slot = (c & 63) + ((c & 128) ? 64 : 0);
    int e    = (c >> 6) & 1;
    base[r * G4 + slot * 2 + e] = v;
}

__global__ __launch_bounds__(256, 2) void gemm_kernel(
    const float* __restrict__ bias_a, const float* __restrict__ bias_b)
{
    const int KI = 8, PPR = 64;
    int tid = threadIdx.x;
    int lane = tid & 31, wid = tid >> 5;
    int tig = lane & 3, gid = lane >> 2;
    int wm = wid & 3, wn = wid >> 2;
    int rb = blockIdx.x * 64 + wm * 16;
    int ntBase = (blockIdx.y * 2 + wn) * 8;

    float acc[8][4];
#pragma unroll
    for (int j = 0; j < 8; j++)
#pragma unroll
        for (int q = 0; q < 4; q++) acc[j][q] = 0.0f;

#pragma unroll
    for (int ki = 0; ki < KI; ki++) {
        uint32_t a[4], al[4];
        size_t r0 = (size_t)(rb + gid) * PPR + ki * 8;
        a[0]  = __ldg(g_xph + r0 + tig);
        a[1]  = __ldg(g_xph + r0 + 8 * PPR + tig);
        a[2]  = __ldg(g_xph + r0 + 4 + tig);
        a[3]  = __ldg(g_xph + r0 + 8 * PPR + 4 + tig);
        al[0] = __ldg(g_xpl + r0 + tig);
        al[1] = __ldg(g_xpl + r0 + 8 * PPR + tig);
        al[2] = __ldg(g_xpl + r0 + 4 + tig);
        al[3] = __ldg(g_xpl + r0 + 8 * PPR + 4 + tig);
#pragma unroll
        for (int j = 0; j < 8; j++) {
            uint4 bf = __ldg(&g_wf1[((ntBase + j) * KI + ki) * 32 + lane]);
            mma16816(acc[j], a,  bf.x, bf.y);
            mma16816(acc[j], a,  bf.z, bf.w);
            mma16816(acc[j], al, bf.x, bf.y);
        }
    }

#pragma unroll
    for (int j = 0; j < 8; j++) {
        int nc = (ntBase + j) * 8 + tig * 2;
        float bs0 = __ldg(bias_a + nc) + __ldg(bias_b + nc);
        float bs1 = __ldg(bias_a + nc + 1) + __ldg(bias_b + nc + 1);
        size_t r = (size_t)(rb + gid);
        st_pair(g_xg1, r,     nc,     acc[j][0] + bs0);
        st_pair(g_xg1, r,     nc + 1, acc[j][1] + bs1);
        st_pair(g_xg1, r + 8, nc,     acc[j][2] + bs0);
        st_pair(g_xg1, r + 8, nc + 1, acc[j][3] + bs1);
    }
}

// ---------------------------------------------------------------------------
// Fused pipelined recurrence (R2 structure):
//  CTA b in [0,64): producer (layer1 rec warps 0-3, layer2-input GEMV warps 4-7)
//  CTA 64+b: consumer (layer2 rec), gated by g_flag[b]
// Changes this round: tanh.approx activations, pipelined dot, release-only flag.
// ---------------------------------------------------------------------------
__global__ __launch_bounds__(256, 1) void fused_rec_kernel(
    const float* __restrict__ Whh1, const float* __restrict__ mask1,
    const float* __restrict__ Wih2, const float* __restrict__ bih2,
    const float* __restrict__ bhh2,
    const float* __restrict__ Whh2, const float* __restrict__ mask2,
    float* __restrict__ out)
{
    __shared__ alignas(16) ull hq[2][64];   // duplicated h: {h,h}

    int tid  = threadIdx.x;
    int bid  = blockIdx.x;
    bool producer = bid < BATCH;
    int b = producer ? bid : bid - BATCH;

    if (producer) {
        if (tid < 128) {
            // ---- layer1 recurrence warps ----
            int lane = tid & 31, w = tid >> 5;
            int jj = (w << 4) + (lane & 15);
            bool isIF = lane < 16;
            int rA = isIF ? jj : 128 + jj;
            ull wv[64];
#pragma unroll
            for (int k = 0; k < 64; k++)
                wv[k] = pack64(__ldg(Whh1 + (size_t)rA * 64 + k),
                               __ldg(Whh1 + (size_t)(rA + 64) * 64 + k));
            if (tid < 64) { hq[0][tid] = 0ull; hq[1][tid] = 0ull; }
            float c = 0.0f;
            const ull* xgb = (const ull*)g_xg1 + (size_t)b * TSTEPS * 128
                             + (isIF ? jj : 64 + jj);
            __syncthreads();                               // bar0
            ull xc = __ldg(xgb), xn = __ldg(xgb + 128);
            for (int t = 0; t < TSTEPS; t++) {
                int p = t & 1;
                ull xf = 0ull;
                if (t + 2 < TSTEPS) xf = __ldg(xgb + (size_t)(t + 2) * 128);
                ull s = add2(dot64p(hq[p], wv), xc);
                float gA, gB; unpack64(s, gA, gB);
                float A0, A1;
                if (isIF) { A0 = sig_mufu(gA);  A1 = sig_mufu(gB); }
                else      { A0 = tanh_mufu(gA); A1 = sig_mufu(gB); }
                float sg = __shfl_xor_sync(0xffffffffu, A0, 16);
                float so = __shfl_xor_sync(0xffffffffu, A1, 16);
                if (isIF) {
                    c = A1 * c + A0 * sg;
                    float h = so * tanh_mufu(c);
                    hq[p ^ 1][jj] = pack64(h, h);
                }
                xc = xn; xn = xf;
                __syncthreads();                           // 1 bar / step
            }
            __syncthreads();                               // post (match gemv)
        } else {
            // ---- GEMV warps: xg2 row t-1 = (W_ih2 * mask1) @ h(t-1) + bias ----
            int s = tid - 128;                             // pair slot 0..127
            int rA = (s < 64) ? s : 128 + (s - 64);
            ull wxv[64];
#pragma unroll
            for (int k = 0; k < 64; k++) {
                float m = __ldg(mask1 + b * 64 + k);
                wxv[k] = pack64(__ldg(Wih2 + (size_t)rA * 64 + k) * m,
                                __ldg(Wih2 + (size_t)(rA + 64) * 64 + k) * m);
            }
            ull bias = pack64(__ldg(bih2 + rA) + __ldg(bhh2 + rA),
                              __ldg(bih2 + rA + 64) + __ldg(bhh2 + rA + 64));
            ull* dst = (ull*)g_xg2 + (size_t)b * TSTEPS * 128 + s;
            __syncthreads();                               // bar0
            for (int t = 0; t < TSTEPS; t++) {
                int p = t & 1;
                if (t > 0) {
                    ull sum = add2(dot64p(hq[p], wxv), bias);
                    dst[(size_t)(t - 1) * 128] = sum;
                }
                if (tid == 128 && t > 0 && (t & 7) == 0) {
                    st_rel(&g_flag[b], (unsigned)(t - 1)); // rows 0..t-2 ready
                }
                __syncthreads();
            }
            {   // final row T-1
                ull sum = add2(dot64p(hq[TSTEPS & 1], wxv), bias);
                dst[(size_t)(TSTEPS - 1) * 128] = sum;
            }
            __syncthreads();                               // post
            if (tid == 128) st_rel(&g_flag[b], (unsigned)TSTEPS);
        }
    } else {
        // =================== CONSUMER: layer2 ===================
        if (tid < 128) {
            int lane = tid & 31, w = tid >> 5;
            int jj = (w << 4) + (lane & 15);
            bool isIF = lane < 16;
            int rA = isIF ? jj : 128 + jj;
            ull wv[64];
#pragma unroll
            for (int k = 0; k < 64; k++)
                wv[k] = pack64(__ldg(Whh2 + (size_t)rA * 64 + k),
                               __ldg(Whh2 + (size_t)(rA + 64) * 64 + k));
            float mval = __ldg(mask2 + b * 64 + jj);
            if (tid < 64) { hq[0][tid] = 0ull; hq[1][tid] = 0ull; }
            float c = 0.0f;
            const ull* xgb = (const ull*)g_xg2 + (size_t)b * TSTEPS * 128
                             + (isIF ? jj : 64 + jj);
            unsigned avail = 0;
            __syncthreads();                               // bar0
            while (avail < 2u) { avail = ld_acq(&g_flag[b]); if (avail < 2u) __nanosleep(32); }
            ull xc = xgb[0], xn = xgb[128];
            for (int t = 0; t < TSTEPS; t++) {
                int p = t & 1;
                ull xf = 0ull;
                if (t + 2 < TSTEPS) {
                    unsigned need = (unsigned)(t + 3);
                    while (avail < need) { avail = ld_acq(&g_flag[b]); if (avail < need) __nanosleep(32); }
                    xf = xgb[(size_t)(t + 2) * 128];
                }
                ull s = add2(dot64p(hq[p], wv), xc);
                float gA, gB; unpack64(s, gA, gB);
                float A0, A1;
                if (isIF) { A0 = sig_mufu(gA);  A1 = sig_mufu(gB); }
                else      { A0 = tanh_mufu(gA); A1 = sig_mufu(gB); }
                float sg = __shfl_xor_sync(0xffffffffu, A0, 16);
                float so = __shfl_xor_sync(0xffffffffu, A1, 16);
                if (isIF) {
                    c = A1 * c + A0 * sg;
                    float h = so * tanh_mufu(c);
                    hq[p ^ 1][jj] = pack64(h, h);
                    out[((size_t)b * TSTEPS + t) * HID + jj] = fmaxf(h * mval, 0.0f);
                }
                xc = xn; xn = xf;
                __syncthreads();
            }
        } else {
            __syncthreads();                               // bar0
            for (int t = 0; t < TSTEPS; t++) __syncthreads();
        }
    }
}

// ---------------------------------------------------------------------------
// Launch
// ---------------------------------------------------------------------------
extern "C" void kernel_launch(void* const* d_in, const int* in_sizes, int n_in,
                              void* d_out, int out_size) {
    const float* x     = (const float*)d_in[0];
    const float* W_ih1 = (const float*)d_in[1];
    const float* W_hh1 = (const float*)d_in[2];
    const float* b_ih1 = (const float*)d_in[3];
    const float* b_hh1 = (const float*)d_in[4];
    const float* W_ih2 = (const float*)d_in[5];
    const float* W_hh2 = (const float*)d_in[6];
    const float* b_ih2 = (const float*)d_in[7];
    const float* b_hh2 = (const float*)d_in[8];
    const float* mask1 = (const float*)d_in[9];
    const float* mask2 = (const float*)d_in[10];
    float* out = (float*)d_out;

    prep_x_kernel<<<(M_ROWS * 64) / 256, 256>>>(x);
    prep_w_kernel<<<(32 * 8 * 32 + 127) / 128, 128>>>(W_ih1);
    gemm_kernel<<<dim3(M_ROWS / 64, 2), 256>>>(b_ih1, b_hh1);
    fused_rec_kernel<<<2 * BATCH, 256>>>(W_hh1, mask1, W_ih2, b_ih2, b_hh2,
                                         W_hh2, mask2, out);
}